// round 12
// baseline (speedup 1.0000x reference)
#include <cuda_runtime.h>
#include <cstdint>
#include <math.h>

#define NB 128
#define NS 256
#define NH 768
#define NL 24

typedef unsigned long long ull;

// Scratch (allocation-free rule: __device__ global)
static __device__ __align__(256) float g_emis[NB * NS * NL];   // 3.1 MB

#define PACK2(out, lo, hi) \
    asm("mov.b64 %0, {%1, %2};" : "=l"(out) : "f"(lo), "f"(hi))
#define UNPACK2(lo, hi, in) \
    asm("mov.b64 {%0, %1}, %2;" : "=f"(lo), "=f"(hi) : "l"(in))
#define ADD2(out, a, b) \
    asm("add.rn.f32x2 %0, %1, %2;" : "=l"(out) : "l"(a), "l"(b))
#define FMA2(acc, a, b) \
    asm("fma.rn.f32x2 %0, %1, %2, %0;" : "+l"(acc) : "l"(a), "l"(b))

// Warp helper: n = min(rowsum(maskA), rowsum(maskB)) for batch b (all lanes)
__device__ __forceinline__ int warp_len(const int* __restrict__ mA,
                                        const int* __restrict__ mB,
                                        int b, int lane) {
    const int4* pa = (const int4*)(mA + b * NS);
    const int4* pb = (const int4*)(mB + b * NS);
    int sa = 0, sb = 0;
#pragma unroll
    for (int i = 0; i < 2; ++i) {
        int4 va = pa[lane + 32 * i];
        int4 vb = pb[lane + 32 * i];
        sa += va.x + va.y + va.z + va.w;
        sb += vb.x + vb.y + vb.z + vb.w;
    }
#pragma unroll
    for (int o = 16; o > 0; o >>= 1) {
        sa += __shfl_xor_sync(0xffffffffu, sa, o);
        sb += __shfl_xor_sync(0xffffffffu, sb, o);
    }
    return (sa < sb) ? sa : sb;
}

// Warp helper: resolve {b, start, end}; b is the all-zero vector.
__device__ __forceinline__ void warp_resolve(const float* __restrict__ v0,
                                             const float* __restrict__ v1,
                                             const float* __restrict__ v2,
                                             int lane, float& xb, float& xs,
                                             float& xe) {
    float x0 = 0.f, x1 = 0.f, x2 = 0.f;
    if (lane < NL) { x0 = v0[lane]; x1 = v1[lane]; x2 = v2[lane]; }
    float a0 = fabsf(x0), a1 = fabsf(x1), a2 = fabsf(x2);
#pragma unroll
    for (int o = 16; o > 0; o >>= 1) {
        a0 += __shfl_xor_sync(0xffffffffu, a0, o);
        a1 += __shfl_xor_sync(0xffffffffu, a1, o);
        a2 += __shfl_xor_sync(0xffffffffu, a2, o);
    }
    int zi = 0;
    if (a0 != 0.f && a1 == 0.f) zi = 1;
    else if (a0 != 0.f && a1 != 0.f && a2 == 0.f) zi = 2;
    xb = (zi == 0) ? x0 : ((zi == 1) ? x1 : x2);
    xs = (zi == 0) ? x1 : x0;
    xe = (zi == 2) ? x1 : x2;
}

// ---------------------------------------------------------------------------
// Kernel 1: emissions. H-split x2 (lane<16 -> H[0:384), lane>=16 -> H[384:768))
// PLUS 2-token register blocking per lane: one W LDS pair feeds 4 FMA2.
// Warp covers 32 tokens; 128 threads/block = 128 tokens; grid (2, NB).
// ---------------------------------------------------------------------------
__global__ __launch_bounds__(128) void k_emis(const float* __restrict__ tf,
                                              const float* __restrict__ W,
                                              const int* __restrict__ mA,
                                              const int* __restrict__ mB,
                                              const float* __restrict__ v0,
                                              const float* __restrict__ v1,
                                              const float* __restrict__ v2) {
    extern __shared__ __align__(16) float w_s[];   // NH*NL = 73728 B
    __shared__ float bias_s[NL];
    int tid = threadIdx.x, lane = tid & 31, wid = tid >> 5;
    int b = blockIdx.y;

    int n = warp_len(mA, mB, b, lane);
    int base = blockIdx.x * 128;
    if (base >= n) return;                         // uniform across block

    if (wid == 0) {
        float xb, xs, xe;
        warp_resolve(v0, v1, v2, lane, xb, xs, xe);
        if (lane < NL) bias_s[lane] = xb;
    }

    {   // stage W: 4608 float4 / 128 threads = 36 each
        const float4* Wv = (const float4*)W;
        float4* ws4 = (float4*)w_s;
#pragma unroll
        for (int i = 0; i < 36; ++i)
            ws4[tid + 128 * i] = Wv[tid + 128 * i];
    }
    __syncthreads();

    int l16 = lane & 15;
    int hh = lane >> 4;                            // H-half
    int tA = base + wid * 32 + l16;                // first token
    int tB = tA + 16;                              // second token
    bool actA = tA < n, actB = tB < n;
    const float* rA = tf + ((size_t)(b * NS) + (actA ? tA + 1 : 1)) * NH + hh * 384;
    const float* rB = tf + ((size_t)(b * NS) + (actB ? tB + 1 : 1)) * NH + hh * 384;

    ull aA[12], aB[12];
#pragma unroll
    for (int i = 0; i < 12; ++i) { aA[i] = 0ull; aB[i] = 0ull; }

    const float* wbase = w_s + hh * 384 * NL;
#pragma unroll 2
    for (int h = 0; h < 384; h += 4) {
        float4 xA = *(const float4*)(rA + h);
        float4 xB = *(const float4*)(rB + h);
        float xa4[4] = {xA.x, xA.y, xA.z, xA.w};
        float xb4[4] = {xB.x, xB.y, xB.z, xB.w};
#pragma unroll
        for (int j = 0; j < 4; ++j) {
            const ulonglong2* wr = (const ulonglong2*)(wbase + (h + j) * NL);
            ull pa, pb;
            PACK2(pa, xa4[j], xa4[j]);
            PACK2(pb, xb4[j], xb4[j]);
#pragma unroll
            for (int q = 0; q < 6; ++q) {
                ulonglong2 w2 = wr[q];
                FMA2(aA[2 * q],     pa, w2.x);
                FMA2(aA[2 * q + 1], pa, w2.y);
                FMA2(aB[2 * q],     pb, w2.x);
                FMA2(aB[2 * q + 1], pb, w2.y);
            }
        }
    }

    // combine H-halves: lane l <-> l+16 hold the same tokens' two halves
    float eA[NL], eB[NL];
#pragma unroll
    for (int i = 0; i < 12; ++i) {
        ull oA = __shfl_xor_sync(0xffffffffu, aA[i], 16);
        ull oB = __shfl_xor_sync(0xffffffffu, aB[i], 16);
        float l1, h1, l2, h2;
        UNPACK2(l1, h1, aA[i]); UNPACK2(l2, h2, oA);
        eA[2 * i] = l1 + l2; eA[2 * i + 1] = h1 + h2;
        UNPACK2(l1, h1, aB[i]); UNPACK2(l2, h2, oB);
        eB[2 * i] = l1 + l2; eB[2 * i + 1] = h1 + h2;
    }

    if (hh == 0) {
#pragma unroll
        for (int l = 0; l < NL; ++l) {
            float bl = bias_s[l];
            eA[l] = 1.f / (1.f + expf(-(eA[l] + bl)));
            eB[l] = 1.f / (1.f + expf(-(eB[l] + bl)));
        }
        if (actA) {
            float* o0 = g_emis + ((size_t)(b * NS) + tA) * NL;
#pragma unroll
            for (int q = 0; q < 6; ++q)
                *(float4*)(o0 + 4 * q) =
                    make_float4(eA[4*q], eA[4*q+1], eA[4*q+2], eA[4*q+3]);
        }
        if (actB) {
            float* o1 = g_emis + ((size_t)(b * NS) + tB) * NL;
#pragma unroll
            for (int q = 0; q < 6; ++q)
                *(float4*)(o1 + 4 * q) =
                    make_float4(eB[4*q], eB[4*q+1], eB[4*q+2], eB[4*q+3]);
        }
    }
}

// ---------------------------------------------------------------------------
// First-index argmax over 24 values (matches jnp.argmax tie rule).
// ---------------------------------------------------------------------------
__device__ __forceinline__ void argmax24(const float* __restrict__ v,
                                         float& best, int& bi) {
    float v12[12]; int i12[12];
#pragma unroll
    for (int i = 0; i < 12; ++i) {
        bool ge = v[2 * i] >= v[2 * i + 1];
        v12[i] = ge ? v[2 * i] : v[2 * i + 1];
        i12[i] = ge ? 2 * i : 2 * i + 1;
    }
    float v6[6]; int i6[6];
#pragma unroll
    for (int i = 0; i < 6; ++i) {
        bool ge = v12[2 * i] >= v12[2 * i + 1];
        v6[i] = ge ? v12[2 * i] : v12[2 * i + 1];
        i6[i] = ge ? i12[2 * i] : i12[2 * i + 1];
    }
    float v3[3]; int i3[3];
#pragma unroll
    for (int i = 0; i < 3; ++i) {
        bool ge = v6[2 * i] >= v6[2 * i + 1];
        v3[i] = ge ? v6[2 * i] : v6[2 * i + 1];
        i3[i] = ge ? i6[2 * i] : i6[2 * i + 1];
    }
    bool g01 = v3[0] >= v3[1];
    float va = g01 ? v3[0] : v3[1];
    int ia = g01 ? i3[0] : i3[1];
    bool gf = va >= v3[2];
    best = gf ? va : v3[2];
    bi = gf ? ia : i3[2];
}

// ---------------------------------------------------------------------------
// Kernel 2: masked Viterbi + backtrace, one warp per batch. Float32 output.
// Candidates = packed f32x2 adds against register-resident Tc; emission
// added once per step (no per-step tcem rebuild).
// ---------------------------------------------------------------------------
__global__ __launch_bounds__(32) void k_vit(const float* __restrict__ trans,
                                            const int* __restrict__ mA,
                                            const int* __restrict__ mB,
                                            const float* __restrict__ v0,
                                            const float* __restrict__ v1,
                                            const float* __restrict__ v2,
                                            float* __restrict__ out) {
    __shared__ __align__(16) float em_s[NS * NL];          // 24576 B
    __shared__ __align__(16) float sbuf[2][32];
    __shared__ unsigned char bp_s[NS * NL];                // 6144 B
    __shared__ int path_s[NS];

    int b = blockIdx.x;
    int lane = threadIdx.x;
    int n = warp_len(mA, mB, b, lane);
    float xb, stt_c, ent_c;
    warp_resolve(v0, v1, v2, lane, xb, stt_c, ent_c);
    int c = lane < NL ? lane : NL - 1;   // lanes 24..31 shadow lane 23

    const float4* src = (const float4*)(g_emis + (size_t)b * NS * NL);
    int n4 = n * 6;
    for (int i = lane; i < n4; i += 32) ((float4*)em_s)[i] = src[i];

    float Tc[NL];
#pragma unroll
    for (int p = 0; p < NL; ++p) Tc[p] = trans[p * NL + c];
    ull Tc_pk[12];
#pragma unroll
    for (int i = 0; i < 12; ++i) PACK2(Tc_pk[i], Tc[2 * i], Tc[2 * i + 1]);

    __syncwarp();

    float s = stt_c + em_s[c];           // score at t=0
    sbuf[0][lane] = s;
    __syncwarp();

    int cur = 0;
    for (int t = 1; t < n; ++t) {
        float em_c = em_s[t * NL + c];   // independent LDS, issues early
        ull sv[12];
        const ulonglong2* sp = (const ulonglong2*)&sbuf[cur][0];
#pragma unroll
        for (int q = 0; q < 6; ++q) {
            ulonglong2 u = sp[q];
            sv[2 * q] = u.x; sv[2 * q + 1] = u.y;
        }
        float cand[NL];
#pragma unroll
        for (int i = 0; i < 12; ++i) {
            ull cp; ADD2(cp, sv[i], Tc_pk[i]);
            UNPACK2(cand[2 * i], cand[2 * i + 1], cp);
        }
        float best; int bi;
        argmax24(cand, best, bi);
        s = best + em_c;
        cur ^= 1;
        sbuf[cur][lane] = s;
        if (lane < NL) bp_s[t * NL + c] = (unsigned char)bi;
        __syncwarp();
    }

    // Final scores + last_tag
    float fin = s + ent_c;
    int fb = cur ^ 1;
    sbuf[fb][lane] = fin;
    __syncwarp();
    float fv[NL];
    const float4* sb2 = (const float4*)(&sbuf[fb][0]);
#pragma unroll
    for (int q = 0; q < 6; ++q) {
        float4 v = sb2[q];
        fv[4 * q] = v.x; fv[4 * q + 1] = v.y;
        fv[4 * q + 2] = v.z; fv[4 * q + 3] = v.w;
    }
    float bv; int last;
    argmax24(fv, bv, last);

    // Backtrace (lane 0)
    if (lane == 0) {
        int tag = last;
        for (int t = n - 1; t >= 1; --t) {
            tag = bp_s[t * NL + tag];
            path_s[t - 1] = tag;
        }
    }
    __syncwarp();

    float* po = out + b * NS;
    for (int t = lane; t < NS; t += 32)
        po[t] = (float)((t >= n - 1) ? last : path_s[t]);
}

// ---------------------------------------------------------------------------
// Size-based input dispatch (robust to permutation).
// ---------------------------------------------------------------------------
extern "C" void kernel_launch(void* const* d_in, const int* in_sizes, int n_in,
                              void* d_out, int out_size) {
    const float* tf = 0;
    const float* W = 0;
    const float* trans = 0;
    const int* mA = 0;
    const int* mB = 0;
    const float* v[3] = {0, 0, 0};
    int nv = 0;

    for (int i = 0; i < n_in; ++i) {
        int sz = in_sizes[i];
        if (sz == NB * NS * NH)      tf = (const float*)d_in[i];
        else if (sz == NH * NL)      W = (const float*)d_in[i];
        else if (sz == NL * NL)      trans = (const float*)d_in[i];
        else if (sz == NB * NS) {
            if (!mA) mA = (const int*)d_in[i];
            else     mB = (const int*)d_in[i];
        }
        else if (sz == NL && nv < 3) v[nv++] = (const float*)d_in[i];
    }
    if (!mB) mB = mA;
    if (!tf || !W || !trans || !mA || nv < 3) return;

    float* out = (float*)d_out;

    static int smem_set = 0;
    if (!smem_set) {
        cudaFuncSetAttribute(k_emis, cudaFuncAttributeMaxDynamicSharedMemorySize,
                             NH * NL * (int)sizeof(float));
        smem_set = 1;
    }

    dim3 ge(2, NB);
    k_emis<<<ge, 128, NH * NL * sizeof(float)>>>(tf, W, mA, mB, v[0], v[1], v[2]);
    k_vit<<<NB, 32>>>(trans, mA, mB, v[0], v[1], v[2], out);
}

// round 13
// speedup vs baseline: 1.0396x; 1.0396x over previous
#include <cuda_runtime.h>
#include <cstdint>
#include <math.h>

#define NB 128
#define NS 256
#define NH 768
#define NL 24
#define XPAD 68            // staged row stride in floats (64 + 4 pad, 272B)
#define NCHUNK 12          // 768 / 64

typedef unsigned long long ull;

// Scratch (allocation-free rule: __device__ global)
static __device__ __align__(256) float g_emis[NB * NS * NL];   // 3.1 MB

#define PACK2(out, lo, hi) \
    asm("mov.b64 %0, {%1, %2};" : "=l"(out) : "f"(lo), "f"(hi))
#define UNPACK2(lo, hi, in) \
    asm("mov.b64 {%0, %1}, %2;" : "=f"(lo), "=f"(hi) : "l"(in))
#define ADD2(out, a, b) \
    asm("add.rn.f32x2 %0, %1, %2;" : "=l"(out) : "l"(a), "l"(b))
#define FMA2(acc, a, b) \
    asm("fma.rn.f32x2 %0, %1, %2, %0;" : "+l"(acc) : "l"(a), "l"(b))

__device__ __forceinline__ void cp_async16(uint32_t dst, const void* src) {
    asm volatile("cp.async.ca.shared.global [%0], [%1], 16;" :: "r"(dst), "l"(src));
}
#define CP_COMMIT() asm volatile("cp.async.commit_group;" ::: "memory")
#define CP_WAIT0()  asm volatile("cp.async.wait_group 0;" ::: "memory")

// Warp helper: n = min(rowsum(maskA), rowsum(maskB)) for batch b (all lanes)
__device__ __forceinline__ int warp_len(const int* __restrict__ mA,
                                        const int* __restrict__ mB,
                                        int b, int lane) {
    const int4* pa = (const int4*)(mA + b * NS);
    const int4* pb = (const int4*)(mB + b * NS);
    int sa = 0, sb = 0;
#pragma unroll
    for (int i = 0; i < 2; ++i) {
        int4 va = pa[lane + 32 * i];
        int4 vb = pb[lane + 32 * i];
        sa += va.x + va.y + va.z + va.w;
        sb += vb.x + vb.y + vb.z + vb.w;
    }
#pragma unroll
    for (int o = 16; o > 0; o >>= 1) {
        sa += __shfl_xor_sync(0xffffffffu, sa, o);
        sb += __shfl_xor_sync(0xffffffffu, sb, o);
    }
    return (sa < sb) ? sa : sb;
}

// Warp helper: resolve {b, start, end}; b is the all-zero vector.
__device__ __forceinline__ void warp_resolve(const float* __restrict__ v0,
                                             const float* __restrict__ v1,
                                             const float* __restrict__ v2,
                                             int lane, float& xb, float& xs,
                                             float& xe) {
    float x0 = 0.f, x1 = 0.f, x2 = 0.f;
    if (lane < NL) { x0 = v0[lane]; x1 = v1[lane]; x2 = v2[lane]; }
    float a0 = fabsf(x0), a1 = fabsf(x1), a2 = fabsf(x2);
#pragma unroll
    for (int o = 16; o > 0; o >>= 1) {
        a0 += __shfl_xor_sync(0xffffffffu, a0, o);
        a1 += __shfl_xor_sync(0xffffffffu, a1, o);
        a2 += __shfl_xor_sync(0xffffffffu, a2, o);
    }
    int zi = 0;
    if (a0 != 0.f && a1 == 0.f) zi = 1;
    else if (a0 != 0.f && a1 != 0.f && a2 == 0.f) zi = 2;
    xb = (zi == 0) ? x0 : ((zi == 1) ? x1 : x2);
    xs = (zi == 0) ? x1 : x0;
    xe = (zi == 2) ? x1 : x2;
}

// ---------------------------------------------------------------------------
// Kernel 1: emissions with smem-staged tf (cp.async, coalesced) + smem W.
// 128 threads, 1 token/thread, grid (2, NB); 12 chunks of 64 h-dims.
// ---------------------------------------------------------------------------
__global__ __launch_bounds__(128) void k_emis(const float* __restrict__ tf,
                                              const float* __restrict__ W,
                                              const int* __restrict__ mA,
                                              const int* __restrict__ mB,
                                              const float* __restrict__ v0,
                                              const float* __restrict__ v1,
                                              const float* __restrict__ v2) {
    extern __shared__ __align__(16) float smem[];
    float* w_s = smem;                       // 18432 floats (72 KB)
    float* x_s = smem + NH * NL;             // 128 * 68 floats (34 KB)
    __shared__ float bias_s[NL];

    int tid = threadIdx.x, lane = tid & 31, wid = tid >> 5;
    int b = blockIdx.y;

    int n = warp_len(mA, mB, b, lane);
    int base = blockIdx.x * 128;
    if (base >= n) return;                   // block-uniform, before barriers

    if (wid == 0) {
        float xb, xs, xe;
        warp_resolve(v0, v1, v2, lane, xb, xs, xe);
        if (lane < NL) bias_s[lane] = xb;
    }

    {   // stage W: 4608 float4 / 128 threads = 36 each (coalesced)
        const float4* Wv = (const float4*)W;
        float4* ws4 = (float4*)w_s;
#pragma unroll
        for (int i = 0; i < 36; ++i)
            ws4[tid + 128 * i] = Wv[tid + 128 * i];
    }

    int t0 = base + tid;
    bool act = t0 < n;
    bool wact = (base + wid * 32) < n;       // warp-uniform activity

    uint32_t xb32 = (uint32_t)__cvta_generic_to_shared(x_s);
    const float* tfb = tf + (size_t)(b * NS) * NH;

    ull a[12];
#pragma unroll
    for (int i = 0; i < 12; ++i) a[i] = 0ull;

    for (int c = 0; c < NCHUNK; ++c) {
        __syncthreads();                     // prev compute done before overwrite
        // stage chunk c: 128 rows x 64 floats (2048 float4), coalesced.
#pragma unroll
        for (int k = 0; k < 16; ++k) {
            int idx = tid + 128 * k;
            int row = idx >> 4;              // 16 float4 per row
            int seg = idx & 15;
            int grow = base + row + 1;
            if (grow > 255) grow = 255;      // clamp: never OOB
            const float* src = tfb + (size_t)grow * NH + c * 64 + seg * 4;
            cp_async16(xb32 + (uint32_t)(row * 272 + seg * 16), src);
        }
        CP_COMMIT();
        CP_WAIT0();
        __syncthreads();

        if (wact) {
            const float* xr = x_s + tid * XPAD;
            const float* wc = w_s + c * 64 * NL;
#pragma unroll 4
            for (int hh = 0; hh < 64; hh += 4) {
                float4 x = *(const float4*)(xr + hh);
                float xs4[4] = {x.x, x.y, x.z, x.w};
#pragma unroll
                for (int j = 0; j < 4; ++j) {
                    const ulonglong2* wr =
                        (const ulonglong2*)(wc + (hh + j) * NL);
                    ull pa;
                    PACK2(pa, xs4[j], xs4[j]);
#pragma unroll
                    for (int q = 0; q < 6; ++q) {
                        ulonglong2 w2 = wr[q];
                        FMA2(a[2 * q],     pa, w2.x);
                        FMA2(a[2 * q + 1], pa, w2.y);
                    }
                }
            }
        }
    }

    if (act) {
        float e[NL];
#pragma unroll
        for (int i = 0; i < 12; ++i) {
            float lo, hi;
            UNPACK2(lo, hi, a[i]);
            e[2 * i] = lo; e[2 * i + 1] = hi;
        }
#pragma unroll
        for (int l = 0; l < NL; ++l)
            e[l] = 1.f / (1.f + expf(-(e[l] + bias_s[l])));
        float* o0 = g_emis + ((size_t)(b * NS) + t0) * NL;
#pragma unroll
        for (int q = 0; q < 6; ++q)
            *(float4*)(o0 + 4 * q) =
                make_float4(e[4*q], e[4*q+1], e[4*q+2], e[4*q+3]);
    }
}

// ---------------------------------------------------------------------------
// First-index argmax over 24 values (matches jnp.argmax tie rule).
// ---------------------------------------------------------------------------
__device__ __forceinline__ void argmax24(const float* __restrict__ v,
                                         float& best, int& bi) {
    float v12[12]; int i12[12];
#pragma unroll
    for (int i = 0; i < 12; ++i) {
        bool ge = v[2 * i] >= v[2 * i + 1];
        v12[i] = ge ? v[2 * i] : v[2 * i + 1];
        i12[i] = ge ? 2 * i : 2 * i + 1;
    }
    float v6[6]; int i6[6];
#pragma unroll
    for (int i = 0; i < 6; ++i) {
        bool ge = v12[2 * i] >= v12[2 * i + 1];
        v6[i] = ge ? v12[2 * i] : v12[2 * i + 1];
        i6[i] = ge ? i12[2 * i] : i12[2 * i + 1];
    }
    float v3[3]; int i3[3];
#pragma unroll
    for (int i = 0; i < 3; ++i) {
        bool ge = v6[2 * i] >= v6[2 * i + 1];
        v3[i] = ge ? v6[2 * i] : v6[2 * i + 1];
        i3[i] = ge ? i6[2 * i] : i6[2 * i + 1];
    }
    bool g01 = v3[0] >= v3[1];
    float va = g01 ? v3[0] : v3[1];
    int ia = g01 ? i3[0] : i3[1];
    bool gf = va >= v3[2];
    best = gf ? va : v3[2];
    bi = gf ? ia : i3[2];
}

// ---------------------------------------------------------------------------
// Kernel 2: masked Viterbi + backtrace, one warp per batch (R12, proven).
// ---------------------------------------------------------------------------
__global__ __launch_bounds__(32) void k_vit(const float* __restrict__ trans,
                                            const int* __restrict__ mA,
                                            const int* __restrict__ mB,
                                            const float* __restrict__ v0,
                                            const float* __restrict__ v1,
                                            const float* __restrict__ v2,
                                            float* __restrict__ out) {
    __shared__ __align__(16) float em_s[NS * NL];          // 24576 B
    __shared__ __align__(16) float sbuf[2][32];
    __shared__ unsigned char bp_s[NS * NL];                // 6144 B
    __shared__ int path_s[NS];

    int b = blockIdx.x;
    int lane = threadIdx.x;
    int n = warp_len(mA, mB, b, lane);
    float xb, stt_c, ent_c;
    warp_resolve(v0, v1, v2, lane, xb, stt_c, ent_c);
    int c = lane < NL ? lane : NL - 1;   // lanes 24..31 shadow lane 23

    const float4* src = (const float4*)(g_emis + (size_t)b * NS * NL);
    int n4 = n * 6;
    for (int i = lane; i < n4; i += 32) ((float4*)em_s)[i] = src[i];

    float Tc[NL];
#pragma unroll
    for (int p = 0; p < NL; ++p) Tc[p] = trans[p * NL + c];
    ull Tc_pk[12];
#pragma unroll
    for (int i = 0; i < 12; ++i) PACK2(Tc_pk[i], Tc[2 * i], Tc[2 * i + 1]);

    __syncwarp();

    float s = stt_c + em_s[c];           // score at t=0
    sbuf[0][lane] = s;
    __syncwarp();

    int cur = 0;
    for (int t = 1; t < n; ++t) {
        float em_c = em_s[t * NL + c];   // independent LDS, issues early
        ull sv[12];
        const ulonglong2* sp = (const ulonglong2*)&sbuf[cur][0];
#pragma unroll
        for (int q = 0; q < 6; ++q) {
            ulonglong2 u = sp[q];
            sv[2 * q] = u.x; sv[2 * q + 1] = u.y;
        }
        float cand[NL];
#pragma unroll
        for (int i = 0; i < 12; ++i) {
            ull cp; ADD2(cp, sv[i], Tc_pk[i]);
            UNPACK2(cand[2 * i], cand[2 * i + 1], cp);
        }
        float best; int bi;
        argmax24(cand, best, bi);
        s = best + em_c;
        cur ^= 1;
        sbuf[cur][lane] = s;
        if (lane < NL) bp_s[t * NL + c] = (unsigned char)bi;
        __syncwarp();
    }

    // Final scores + last_tag
    float fin = s + ent_c;
    int fb = cur ^ 1;
    sbuf[fb][lane] = fin;
    __syncwarp();
    float fv[NL];
    const float4* sb2 = (const float4*)(&sbuf[fb][0]);
#pragma unroll
    for (int q = 0; q < 6; ++q) {
        float4 v = sb2[q];
        fv[4 * q] = v.x; fv[4 * q + 1] = v.y;
        fv[4 * q + 2] = v.z; fv[4 * q + 3] = v.w;
    }
    float bv; int last;
    argmax24(fv, bv, last);

    // Backtrace (lane 0)
    if (lane == 0) {
        int tag = last;
        for (int t = n - 1; t >= 1; --t) {
            tag = bp_s[t * NL + tag];
            path_s[t - 1] = tag;
        }
    }
    __syncwarp();

    float* po = out + b * NS;
    for (int t = lane; t < NS; t += 32)
        po[t] = (float)((t >= n - 1) ? last : path_s[t]);
}

// ---------------------------------------------------------------------------
// Size-based input dispatch (robust to permutation).
// ---------------------------------------------------------------------------
extern "C" void kernel_launch(void* const* d_in, const int* in_sizes, int n_in,
                              void* d_out, int out_size) {
    const float* tf = 0;
    const float* W = 0;
    const float* trans = 0;
    const int* mA = 0;
    const int* mB = 0;
    const float* v[3] = {0, 0, 0};
    int nv = 0;

    for (int i = 0; i < n_in; ++i) {
        int sz = in_sizes[i];
        if (sz == NB * NS * NH)      tf = (const float*)d_in[i];
        else if (sz == NH * NL)      W = (const float*)d_in[i];
        else if (sz == NL * NL)      trans = (const float*)d_in[i];
        else if (sz == NB * NS) {
            if (!mA) mA = (const int*)d_in[i];
            else     mB = (const int*)d_in[i];
        }
        else if (sz == NL && nv < 3) v[nv++] = (const float*)d_in[i];
    }
    if (!mB) mB = mA;
    if (!tf || !W || !trans || !mA || nv < 3) return;

    float* out = (float*)d_out;

    const int SMEM_EMIS = (NH * NL + 128 * XPAD) * (int)sizeof(float); // 108544
    static int smem_set = 0;
    if (!smem_set) {
        cudaFuncSetAttribute(k_emis, cudaFuncAttributeMaxDynamicSharedMemorySize,
                             SMEM_EMIS);
        smem_set = 1;
    }

    dim3 ge(2, NB);
    k_emis<<<ge, 128, SMEM_EMIS>>>(tf, W, mA, mB, v[0], v[1], v[2]);
    k_vit<<<NB, 32>>>(trans, mA, mB, v[0], v[1], v[2], out);
}